// round 2
// baseline (speedup 1.0000x reference)
#include <cuda_runtime.h>
#include <cstdint>

// Problem constants
#define BATCH 8
#define MDIM  512
#define WDIM  512
#define LCH   31
#define WOUT  (WDIM + LCH - 1)            // 542
#define ROWF  (WDIM * LCH)                // 15872 floats per (b,m) row
#define ROW4  (ROWF / 4)                  // 3968 float4
#define YELEMS ((long long)BATCH * MDIM * WOUT)          // 2,220,032
#define HELEMS ((long long)MDIM * WDIM * LCH)            // 8,126,464
#define SMEM_BYTES (ROWF * sizeof(float))                // 63488

__device__ int g_maxbits;

__global__ void cassi_init_max() { g_maxbits = 0; }

__global__ __launch_bounds__(256, 3)
void cassi_main(const float* __restrict__ X, const float* __restrict__ H,
                float* __restrict__ Y) {
    extern __shared__ float aux[];           // 15872 floats: product row
    __shared__ int smax;

    const int bm = blockIdx.x;               // 0 .. 4095  (b*512 + m)
    const int m  = bm & (MDIM - 1);

    if (threadIdx.x == 0) smax = 0;

    // Coalesced load + elementwise product into smem
    const float4* X4 = reinterpret_cast<const float4*>(X) + (long long)bm * ROW4;
    const float4* H4 = reinterpret_cast<const float4*>(H) + (long long)m * ROW4;
    float4* A4 = reinterpret_cast<float4*>(aux);
    #pragma unroll 4
    for (int j = threadIdx.x; j < ROW4; j += blockDim.x) {
        float4 x = X4[j];
        float4 h = H4[j];
        float4 a;
        a.x = x.x * h.x; a.y = x.y * h.y; a.z = x.z * h.z; a.w = x.w * h.w;
        A4[j] = a;
    }
    __syncthreads();

    // Shift-and-sum: Y[w] = sum_i aux[(w-i)*31 + i] = sum_i aux[w*31 - 30*i]
    // Lane stride 31 words (coprime with 32 banks) -> conflict-free LDS.
    float lmax = 0.f;
    float* yrow = Y + (long long)bm * WOUT;
    for (int w = threadIdx.x; w < WOUT; w += blockDim.x) {
        float acc = 0.f;
        if (w >= LCH - 1 && w < WDIM) {
            // full 31-term case (482 of 542 outputs) - unrolled
            int addr = w * LCH;
            #pragma unroll
            for (int i = 0; i < LCH; ++i) { acc += aux[addr]; addr -= (LCH - 1); }
        } else {
            int ilo = max(0, w - (WDIM - 1));
            int ihi = min(LCH - 1, w);
            int addr = (w - ilo) * LCH + ilo;
            for (int i = ilo; i <= ihi; ++i) { acc += aux[addr]; addr -= (LCH - 1); }
        }
        yrow[w] = acc;
        lmax = fmaxf(lmax, acc);
    }

    // Reduce max: warp shuffle -> shared atomic -> one global atomic per block.
    #pragma unroll
    for (int off = 16; off > 0; off >>= 1)
        lmax = fmaxf(lmax, __shfl_xor_sync(0xFFFFFFFFu, lmax, off));
    if ((threadIdx.x & 31) == 0)
        atomicMax(&smax, __float_as_int(lmax));   // all values >= 0
    __syncthreads();
    if (threadIdx.x == 0)
        atomicMax(&g_maxbits, smax);
}

__global__ void cassi_norm(float4* __restrict__ Y4, int n4) {
    const float inv = __frcp_rn(__int_as_float(g_maxbits));
    int i = blockIdx.x * blockDim.x + threadIdx.x;
    if (i < n4) {
        float4 v = Y4[i];
        v.x *= inv; v.y *= inv; v.z *= inv; v.w *= inv;
        Y4[i] = v;
    }
}

extern "C" void kernel_launch(void* const* d_in, const int* in_sizes, int n_in,
                              void* d_out, int out_size) {
    // Identify X (big) and H (small) defensively by element count.
    const float* X = (const float*)d_in[0];
    const float* H = (const float*)d_in[1];
    if (n_in >= 2 && in_sizes[0] < in_sizes[1]) {
        X = (const float*)d_in[1];
        H = (const float*)d_in[0];
    }
    float* Y = (float*)d_out;

    cudaFuncSetAttribute(cassi_main, cudaFuncAttributeMaxDynamicSharedMemorySize,
                         (int)SMEM_BYTES);

    cassi_init_max<<<1, 1>>>();
    cassi_main<<<BATCH * MDIM, 256, SMEM_BYTES>>>(X, H, Y);

    const int n4 = (int)(YELEMS / 4);                    // 555008, exact
    cassi_norm<<<(n4 + 255) / 256, 256>>>((float4*)Y, n4);

    // Tuple output (Y, H5): append H verbatim if the out buffer has room.
    if ((long long)out_size >= YELEMS + HELEMS) {
        cudaMemcpyAsync((char*)d_out + YELEMS * sizeof(float), H,
                        HELEMS * sizeof(float), cudaMemcpyDeviceToDevice);
    }
}

// round 3
// speedup vs baseline: 1.0755x; 1.0755x over previous
#include <cuda_runtime.h>
#include <cstdint>

// Problem constants
#define BATCH 8
#define MDIM  512
#define WDIM  512
#define LCH   31
#define WOUT  (WDIM + LCH - 1)            // 542
#define ROWF  (WDIM * LCH)                // 15872 floats per (b,m) row
#define ROW4  (ROWF / 4)                  // 3968 float4
#define YELEMS ((long long)BATCH * MDIM * WOUT)          // 2,220,032 (divisible by 4)
#define HELEMS ((long long)MDIM * WDIM * LCH)            // 8,126,464
#define SMEM_BYTES (ROWF * sizeof(float))                // 63488
#define NORM_BLOCK 256
#define N4 ((int)(YELEMS / 4))                           // 555008 = 2168 * 256 exact

__device__ int g_maxbits;       // zero-initialized once by CUDA runtime
__device__ unsigned g_done;     // ditto; both self-reset each replay

__global__ __launch_bounds__(512, 3)
void cassi_main(const float* __restrict__ X, const float* __restrict__ H,
                float* __restrict__ Y, float* __restrict__ Hout) {
    extern __shared__ float aux[];           // 15872 floats: product row
    __shared__ int smax;

    const int bm = blockIdx.x;               // 0 .. 4095  (b*512 + m)
    const int m  = bm & (MDIM - 1);

    if (threadIdx.x == 0) smax = 0;

    // Coalesced load + elementwise product into smem.
    // Blocks with b==0 also emit the H5 output (replaces a separate memcpy).
    const float4* X4 = reinterpret_cast<const float4*>(X) + (long long)bm * ROW4;
    const float4* H4 = reinterpret_cast<const float4*>(H) + (long long)m * ROW4;
    float4* A4 = reinterpret_cast<float4*>(aux);
    if (bm < MDIM) {
        float4* HO4 = reinterpret_cast<float4*>(Hout) + (long long)m * ROW4;
        #pragma unroll 4
        for (int j = threadIdx.x; j < ROW4; j += blockDim.x) {
            float4 x = X4[j];
            float4 h = H4[j];
            float4 a;
            a.x = x.x * h.x; a.y = x.y * h.y; a.z = x.z * h.z; a.w = x.w * h.w;
            A4[j] = a;
            HO4[j] = h;
        }
    } else {
        #pragma unroll 4
        for (int j = threadIdx.x; j < ROW4; j += blockDim.x) {
            float4 x = X4[j];
            float4 h = H4[j];
            float4 a;
            a.x = x.x * h.x; a.y = x.y * h.y; a.z = x.z * h.z; a.w = x.w * h.w;
            A4[j] = a;
        }
    }
    __syncthreads();

    // Shift-and-sum: Y[w] = sum_i aux[(w-i)*31 + i] = aux[w*31 - 30*i]
    // Lane stride 31 words (coprime with 32 banks) -> conflict-free LDS.
    float lmax = 0.f;
    float* yrow = Y + (long long)bm * WOUT;
    for (int w = threadIdx.x; w < WOUT; w += blockDim.x) {
        float acc = 0.f;
        if (w >= LCH - 1 && w < WDIM) {
            int addr = w * LCH;
            #pragma unroll
            for (int i = 0; i < LCH; ++i) { acc += aux[addr]; addr -= (LCH - 1); }
        } else {
            int ilo = max(0, w - (WDIM - 1));
            int ihi = min(LCH - 1, w);
            int addr = (w - ilo) * LCH + ilo;
            for (int i = ilo; i <= ihi; ++i) { acc += aux[addr]; addr -= (LCH - 1); }
        }
        yrow[w] = acc;
        lmax = fmaxf(lmax, acc);
    }

    // Reduce max: warp shuffle -> shared atomic -> one global atomic per block.
    #pragma unroll
    for (int off = 16; off > 0; off >>= 1)
        lmax = fmaxf(lmax, __shfl_xor_sync(0xFFFFFFFFu, lmax, off));
    if ((threadIdx.x & 31) == 0)
        atomicMax(&smax, __float_as_int(lmax));   // all values >= 0
    __syncthreads();
    if (threadIdx.x == 0)
        atomicMax(&g_maxbits, smax);
}

__global__ __launch_bounds__(NORM_BLOCK)
void cassi_norm(float4* __restrict__ Y4) {
    const float inv = __frcp_rn(__int_as_float(g_maxbits));  // read BEFORE any reset
    int i = blockIdx.x * blockDim.x + threadIdx.x;
    float4 v = Y4[i];
    v.x *= inv; v.y *= inv; v.z *= inv; v.w *= inv;
    Y4[i] = v;

    // Self-reset for the next graph replay: last block to finish zeroes state.
    __threadfence();
    __syncthreads();
    if (threadIdx.x == 0) {
        if (atomicAdd(&g_done, 1u) == gridDim.x - 1) {
            g_maxbits = 0;
            g_done = 0;
            __threadfence();
        }
    }
}

extern "C" void kernel_launch(void* const* d_in, const int* in_sizes, int n_in,
                              void* d_out, int out_size) {
    // Identify X (big) and H (small) defensively by element count.
    const float* X = (const float*)d_in[0];
    const float* H = (const float*)d_in[1];
    if (n_in >= 2 && in_sizes[0] < in_sizes[1]) {
        X = (const float*)d_in[1];
        H = (const float*)d_in[0];
    }
    float* Y = (float*)d_out;
    float* Hout = Y + YELEMS;   // H5 region of the tuple output

    cudaFuncSetAttribute(cassi_main, cudaFuncAttributeMaxDynamicSharedMemorySize,
                         (int)SMEM_BYTES);

    cassi_main<<<BATCH * MDIM, 512, SMEM_BYTES>>>(X, H, Y, Hout);
    cassi_norm<<<N4 / NORM_BLOCK, NORM_BLOCK>>>((float4*)Y);
}

// round 5
// speedup vs baseline: 1.1889x; 1.1054x over previous
#include <cuda_runtime.h>
#include <cstdint>

// Problem constants
#define BATCH 8
#define MDIM  512
#define WDIM  512
#define LCH   31
#define WOUT  (WDIM + LCH - 1)            // 542
#define ROWF  (WDIM * LCH)                // 15872 floats per (b,m) row
#define ROW4  (ROWF / 4)                  // 3968 float4
#define YELEMS ((long long)BATCH * MDIM * WOUT)          // 2,220,032 (divisible by 4)
#define HELEMS ((long long)MDIM * WDIM * LCH)            // 8,126,464
#define SMEM_BYTES (ROWF * sizeof(float))                // 63488
#define NORM_BLOCK 256
#define N4 ((int)(YELEMS / 4))                           // 555008 = 2168 * 256 exact

__device__ int g_maxbits;       // zero-initialized at module load; self-reset each replay
__device__ unsigned g_done;

__global__ __launch_bounds__(512, 3)
void cassi_main(const float* __restrict__ X, const float* __restrict__ H,
                float* __restrict__ Y, float* __restrict__ Hout) {
    extern __shared__ float aux[];           // 15872 floats: product row
    __shared__ int smax;

    const int bm = blockIdx.x;               // 0 .. 4095  (b*512 + m)
    const int m  = bm & (MDIM - 1);

    if (threadIdx.x == 0) smax = 0;

    // Coalesced load + elementwise product into smem.
    // X is streamed once -> evict-first (__ldcs) so it doesn't thrash H out of L2.
    // H is re-read by all 8 batches -> default policy, keep resident in L2.
    const float4* X4 = reinterpret_cast<const float4*>(X) + (long long)bm * ROW4;
    const float4* H4 = reinterpret_cast<const float4*>(H) + (long long)m * ROW4;
    float4* A4 = reinterpret_cast<float4*>(aux);
    if (bm < MDIM) {
        float4* HO4 = reinterpret_cast<float4*>(Hout) + (long long)m * ROW4;
        #pragma unroll 4
        for (int j = threadIdx.x; j < ROW4; j += blockDim.x) {
            float4 x = __ldcs(&X4[j]);
            float4 h = H4[j];
            float4 a;
            a.x = x.x * h.x; a.y = x.y * h.y; a.z = x.z * h.z; a.w = x.w * h.w;
            A4[j] = a;
            __stcs(&HO4[j], h);              // write-once, never re-read
        }
    } else {
        #pragma unroll 4
        for (int j = threadIdx.x; j < ROW4; j += blockDim.x) {
            float4 x = __ldcs(&X4[j]);
            float4 h = H4[j];
            float4 a;
            a.x = x.x * h.x; a.y = x.y * h.y; a.z = x.z * h.z; a.w = x.w * h.w;
            A4[j] = a;
        }
    }
    __syncthreads();

    // Shift-and-sum: Y[w] = sum_i aux[(w-i)*31 + i] = aux[w*31 - 30*i]
    // Lane stride 31 words (coprime with 32 banks) -> conflict-free LDS.
    float lmax = 0.f;
    float* yrow = Y + (long long)bm * WOUT;
    for (int w = threadIdx.x; w < WOUT; w += blockDim.x) {
        float acc = 0.f;
        if (w >= LCH - 1 && w < WDIM) {
            int addr = w * LCH;
            #pragma unroll
            for (int i = 0; i < LCH; ++i) { acc += aux[addr]; addr -= (LCH - 1); }
        } else {
            int ilo = max(0, w - (WDIM - 1));
            int ihi = min(LCH - 1, w);
            int addr = (w - ilo) * LCH + ilo;
            for (int i = ilo; i <= ihi; ++i) { acc += aux[addr]; addr -= (LCH - 1); }
        }
        yrow[w] = acc;                       // default policy: norm re-reads Y from L2
        lmax = fmaxf(lmax, acc);
    }

    // Reduce max: warp shuffle -> shared atomic -> one global atomic per block.
    #pragma unroll
    for (int off = 16; off > 0; off >>= 1)
        lmax = fmaxf(lmax, __shfl_xor_sync(0xFFFFFFFFu, lmax, off));
    if ((threadIdx.x & 31) == 0)
        atomicMax(&smax, __float_as_int(lmax));   // all values >= 0
    __syncthreads();
    if (threadIdx.x == 0)
        atomicMax(&g_maxbits, smax);
}

__global__ __launch_bounds__(NORM_BLOCK)
void cassi_norm(float4* __restrict__ Y4) {
    const float inv = __frcp_rn(__int_as_float(g_maxbits));
    int i = blockIdx.x * blockDim.x + threadIdx.x;
    float4 v = Y4[i];
    v.x *= inv; v.y *= inv; v.z *= inv; v.w *= inv;
    Y4[i] = v;

    // Self-reset for the next graph replay. No fence needed: every thread in
    // this block consumed g_maxbits before __syncthreads(), and thread 0's
    // atomicAdd is ordered after the barrier; the LAST increment therefore
    // implies all 2168 blocks have already read g_maxbits.
    __syncthreads();
    if (threadIdx.x == 0) {
        if (atomicAdd(&g_done, 1u) == gridDim.x - 1) {
            g_maxbits = 0;
            g_done = 0;
        }
    }
}

extern "C" void kernel_launch(void* const* d_in, const int* in_sizes, int n_in,
                              void* d_out, int out_size) {
    // Identify X (big) and H (small) defensively by element count.
    const float* X = (const float*)d_in[0];
    const float* H = (const float*)d_in[1];
    if (n_in >= 2 && in_sizes[0] < in_sizes[1]) {
        X = (const float*)d_in[1];
        H = (const float*)d_in[0];
    }
    float* Y = (float*)d_out;
    float* Hout = Y + YELEMS;   // H5 region of the tuple output

    cudaFuncSetAttribute(cassi_main, cudaFuncAttributeMaxDynamicSharedMemorySize,
                         (int)SMEM_BYTES);

    cassi_main<<<BATCH * MDIM, 512, SMEM_BYTES>>>(X, H, Y, Hout);
    cassi_norm<<<N4 / NORM_BLOCK, NORM_BLOCK>>>((float4*)Y);
}

// round 6
// speedup vs baseline: 1.1909x; 1.0017x over previous
#include <cuda_runtime.h>
#include <cstdint>

// Problem constants
#define BATCH 8
#define MDIM  512
#define WDIM  512
#define LCH   31
#define WOUT  (WDIM + LCH - 1)            // 542
#define ROWF  (WDIM * LCH)                // 15872 floats per (b,m) row
#define ROW4  (ROWF / 4)                  // 3968 float4
#define YELEMS ((long long)BATCH * MDIM * WOUT)          // 2,220,032 (divisible by 4)
#define HELEMS ((long long)MDIM * WDIM * LCH)            // 8,126,464
#define SMEM_BYTES (ROWF * sizeof(float))                // 63488
#define NORM_BLOCK 256
#define NORM_VEC 8                                        // float4 per thread
#define N4 ((int)(YELEMS / 4))                           // 555008 = 271 * 256 * 8 exact
#define NORM_GRID (N4 / (NORM_BLOCK * NORM_VEC))         // 271

__device__ int g_maxbits;       // zero-initialized at module load; self-reset each replay
__device__ unsigned g_done;

__global__ __launch_bounds__(512, 3)
void cassi_main(const float* __restrict__ X, const float* __restrict__ H,
                float* __restrict__ Y, float* __restrict__ Hout) {
    extern __shared__ float aux[];           // 15872 floats: product row
    __shared__ int smax;

    const int bm = blockIdx.x;               // 0 .. 4095  (b*512 + m)
    const int m  = bm & (MDIM - 1);

    if (threadIdx.x == 0) smax = 0;

    // Coalesced load + elementwise product into smem.
    // X is streamed once -> evict-first (__ldcs) so it doesn't thrash H out of L2.
    // H is re-read by all 8 batches -> default policy, keep resident in L2.
    const float4* X4 = reinterpret_cast<const float4*>(X) + (long long)bm * ROW4;
    const float4* H4 = reinterpret_cast<const float4*>(H) + (long long)m * ROW4;
    float4* A4 = reinterpret_cast<float4*>(aux);
    if (bm < MDIM) {
        float4* HO4 = reinterpret_cast<float4*>(Hout) + (long long)m * ROW4;
        #pragma unroll 4
        for (int j = threadIdx.x; j < ROW4; j += blockDim.x) {
            float4 x = __ldcs(&X4[j]);
            float4 h = H4[j];
            float4 a;
            a.x = x.x * h.x; a.y = x.y * h.y; a.z = x.z * h.z; a.w = x.w * h.w;
            A4[j] = a;
            __stcs(&HO4[j], h);              // write-once, never re-read
        }
    } else {
        #pragma unroll 4
        for (int j = threadIdx.x; j < ROW4; j += blockDim.x) {
            float4 x = __ldcs(&X4[j]);
            float4 h = H4[j];
            float4 a;
            a.x = x.x * h.x; a.y = x.y * h.y; a.z = x.z * h.z; a.w = x.w * h.w;
            A4[j] = a;
        }
    }
    __syncthreads();

    // Shift-and-sum: Y[w] = sum_i aux[(w-i)*31 + i] = aux[w*31 - 30*i]
    // Lane stride 31 words (coprime with 32 banks) -> conflict-free LDS.
    float lmax = 0.f;
    float* yrow = Y + (long long)bm * WOUT;
    for (int w = threadIdx.x; w < WOUT; w += blockDim.x) {
        float acc = 0.f;
        if (w >= LCH - 1 && w < WDIM) {
            int addr = w * LCH;
            #pragma unroll
            for (int i = 0; i < LCH; ++i) { acc += aux[addr]; addr -= (LCH - 1); }
        } else {
            int ilo = max(0, w - (WDIM - 1));
            int ihi = min(LCH - 1, w);
            int addr = (w - ilo) * LCH + ilo;
            for (int i = ilo; i <= ihi; ++i) { acc += aux[addr]; addr -= (LCH - 1); }
        }
        yrow[w] = acc;                       // default policy: norm re-reads Y from L2
        lmax = fmaxf(lmax, acc);
    }

    // Reduce max: warp shuffle -> shared atomic -> one global atomic per block.
    #pragma unroll
    for (int off = 16; off > 0; off >>= 1)
        lmax = fmaxf(lmax, __shfl_xor_sync(0xFFFFFFFFu, lmax, off));
    if ((threadIdx.x & 31) == 0)
        atomicMax(&smax, __float_as_int(lmax));   // all values >= 0
    __syncthreads();
    if (threadIdx.x == 0)
        atomicMax(&g_maxbits, smax);
}

__global__ __launch_bounds__(NORM_BLOCK)
void cassi_norm(float4* __restrict__ Y4) {
    // Each block owns a contiguous span of NORM_BLOCK*NORM_VEC float4s.
    // 8 independent load chains per thread (MLP=8) amortize memory latency;
    // 271 blocks instead of 2168 cut the contended tail atomics 8x.
    const int base = blockIdx.x * (NORM_BLOCK * NORM_VEC) + threadIdx.x;

    float4 v[NORM_VEC];
    #pragma unroll
    for (int k = 0; k < NORM_VEC; ++k)
        v[k] = Y4[base + k * NORM_BLOCK];

    const float inv = __frcp_rn(__int_as_float(g_maxbits));
    #pragma unroll
    for (int k = 0; k < NORM_VEC; ++k) {
        v[k].x *= inv; v[k].y *= inv; v[k].z *= inv; v[k].w *= inv;
        Y4[base + k * NORM_BLOCK] = v[k];
    }

    // Self-reset for the next graph replay. No fence needed: every thread in
    // this block consumed g_maxbits before __syncthreads(), and thread 0's
    // atomicAdd is ordered after the barrier; the LAST increment therefore
    // implies all blocks have already read g_maxbits.
    __syncthreads();
    if (threadIdx.x == 0) {
        if (atomicAdd(&g_done, 1u) == gridDim.x - 1) {
            g_maxbits = 0;
            g_done = 0;
        }
    }
}

extern "C" void kernel_launch(void* const* d_in, const int* in_sizes, int n_in,
                              void* d_out, int out_size) {
    // Identify X (big) and H (small) defensively by element count.
    const float* X = (const float*)d_in[0];
    const float* H = (const float*)d_in[1];
    if (n_in >= 2 && in_sizes[0] < in_sizes[1]) {
        X = (const float*)d_in[1];
        H = (const float*)d_in[0];
    }
    float* Y = (float*)d_out;
    float* Hout = Y + YELEMS;   // H5 region of the tuple output

    cudaFuncSetAttribute(cassi_main, cudaFuncAttributeMaxDynamicSharedMemorySize,
                         (int)SMEM_BYTES);

    cassi_main<<<BATCH * MDIM, 512, SMEM_BYTES>>>(X, H, Y, Hout);
    cassi_norm<<<NORM_GRID, NORM_BLOCK>>>((float4*)Y);
}